// round 4
// baseline (speedup 1.0000x reference)
#include <cuda_runtime.h>
#include <math.h>

#define NB 4
#define CIN 256
#define CO 256
#define HDIM 56
#define WDIM 56
#define HW 3136
#define NCOL 12544     // NB*HW
#define NHEAD 2
#define HD 128
#define EPS 1e-5f
#define SEH 16

// ---------------- scratch (device globals, no allocation) ----------------
__device__ float g_qt[NCOL * CO];   // [n][c] transposed
__device__ float g_kt[NCOL * CO];
__device__ float g_vt[NCOL * CO];
__device__ float g_y1[NB * CO * HW]; // after attn + BN1 + relu, channel-major
__device__ float g_y2[NB * CO * HW]; // after agg conv + BN2, channel-major
__device__ float g_s [NB * SEH * HW];
__device__ float g_p [NB * SEH];
__device__ float g_g [NB * SEH];

// ---------------- GEMM: q/k/v = W @ x, write TRANSPOSED [n][256] ----------------
__global__ void gemm_qkv_kernel(const float* __restrict__ Wq,
                                const float* __restrict__ Wk,
                                const float* __restrict__ Wv,
                                const float* __restrict__ x) {
    const float* Wm = (blockIdx.z == 0) ? Wq : (blockIdx.z == 1 ? Wk : Wv);
    float* outp = (blockIdx.z == 0) ? g_qt : (blockIdx.z == 1 ? g_kt : g_vt);

    __shared__ float As[64][17];  // [o_local][c_local], padded
    __shared__ float Bs[16][64];  // [c_local][n_local]

    int tid = threadIdx.x;
    int tx = tid & 15, ty = tid >> 4;
    int o0 = blockIdx.y * 64;
    int n0 = blockIdx.x * 64;        // 3136 % 64 == 0: tile never crosses batch
    int bb = n0 / HW;
    int hw0 = n0 % HW;
    const float* xb = x + (size_t)bb * CIN * HW + hw0;

    int arow = tid >> 2, aseg = tid & 3;
    int brow = tid >> 4, bseg = tid & 15;

    float acc[4][4];
#pragma unroll
    for (int i = 0; i < 4; i++)
#pragma unroll
        for (int j = 0; j < 4; j++) acc[i][j] = 0.f;

    for (int k0 = 0; k0 < CIN; k0 += 16) {
        float4 av = *(const float4*)&Wm[(o0 + arow) * CIN + k0 + aseg * 4];
        float4 bv = *(const float4*)&xb[(size_t)(k0 + brow) * HW + bseg * 4];
        __syncthreads();
        As[arow][aseg * 4 + 0] = av.x;
        As[arow][aseg * 4 + 1] = av.y;
        As[arow][aseg * 4 + 2] = av.z;
        As[arow][aseg * 4 + 3] = av.w;
        *(float4*)&Bs[brow][bseg * 4] = bv;
        __syncthreads();
#pragma unroll
        for (int c = 0; c < 16; c++) {
            float a0 = As[ty * 4 + 0][c];
            float a1 = As[ty * 4 + 1][c];
            float a2 = As[ty * 4 + 2][c];
            float a3 = As[ty * 4 + 3][c];
            float4 b4 = *(float4*)&Bs[c][tx * 4];
            acc[0][0] += a0 * b4.x; acc[0][1] += a0 * b4.y; acc[0][2] += a0 * b4.z; acc[0][3] += a0 * b4.w;
            acc[1][0] += a1 * b4.x; acc[1][1] += a1 * b4.y; acc[1][2] += a1 * b4.z; acc[1][3] += a1 * b4.w;
            acc[2][0] += a2 * b4.x; acc[2][1] += a2 * b4.y; acc[2][2] += a2 * b4.z; acc[2][3] += a2 * b4.w;
            acc[3][0] += a3 * b4.x; acc[3][1] += a3 * b4.y; acc[3][2] += a3 * b4.z; acc[3][3] += a3 * b4.w;
        }
    }
    // transposed store: out[n][o], 4 consecutive o per float4
#pragma unroll
    for (int j = 0; j < 4; j++) {
        float4 v;
        v.x = acc[0][j]; v.y = acc[1][j]; v.z = acc[2][j]; v.w = acc[3][j];
        *(float4*)&outp[(size_t)(n0 + tx * 4 + j) * CO + o0 + ty * 4] = v;
    }
}

// ---------------- attention: warp per (b, head, h, w) ----------------
__global__ void attn_kernel(const float* __restrict__ rel_h,
                            const float* __restrict__ rel_w,
                            const float* __restrict__ g1, const float* __restrict__ b1,
                            const float* __restrict__ m1, const float* __restrict__ v1) {
    int wid = blockIdx.x * 8 + (threadIdx.x >> 5);
    int lane = threadIdx.x & 31;
    int b = wid / (NHEAD * HW);
    int r = wid % (NHEAD * HW);
    int nh = r / HW;
    int hw = r % HW;
    int h = hw / WDIM, w = hw % WDIM;

    const float4 q4 = *(const float4*)&g_qt[(size_t)(b * HW + hw) * CO + nh * HD + lane * 4];
    const float* rel = nh ? rel_w : rel_h;   // [c][tap], size 128*5

    // bias[t] = sum_c q[c] * rel[c][t]
    float bias[5];
#pragma unroll
    for (int t = 0; t < 5; t++) {
        int c = lane * 4;
        float p = q4.x * rel[(c + 0) * 5 + t] + q4.y * rel[(c + 1) * 5 + t]
                + q4.z * rel[(c + 2) * 5 + t] + q4.w * rel[(c + 3) * 5 + t];
#pragma unroll
        for (int m = 16; m; m >>= 1) p += __shfl_xor_sync(0xffffffffu, p, m);
        bias[t] = p;
    }

    float sc[25];
#pragma unroll
    for (int ki = 0; ki < 5; ki++) {
        int hh = h + ki - 2;
#pragma unroll
        for (int kj = 0; kj < 5; kj++) {
            int ww = w + kj - 2;
            bool inb = (hh >= 0 && hh < HDIM && ww >= 0 && ww < WDIM);
            float p = 0.f;
            if (inb) {
                const float4 k4 = *(const float4*)
                    &g_kt[(size_t)(b * HW + hh * WDIM + ww) * CO + nh * HD + lane * 4];
                p = q4.x * k4.x + q4.y * k4.y + q4.z * k4.z + q4.w * k4.w;
            }
#pragma unroll
            for (int m = 16; m; m >>= 1) p += __shfl_xor_sync(0xffffffffu, p, m);
            sc[ki * 5 + kj] = (p + bias[nh ? kj : ki]) * 0.08838834764831845f;
        }
    }

    float mx = sc[0];
#pragma unroll
    for (int i = 1; i < 25; i++) mx = fmaxf(mx, sc[i]);
    float sum = 0.f;
#pragma unroll
    for (int i = 0; i < 25; i++) { sc[i] = __expf(sc[i] - mx); sum += sc[i]; }
    float inv = 1.f / sum;

    float4 acc = make_float4(0.f, 0.f, 0.f, 0.f);
#pragma unroll
    for (int ki = 0; ki < 5; ki++) {
        int hh = h + ki - 2;
#pragma unroll
        for (int kj = 0; kj < 5; kj++) {
            int ww = w + kj - 2;
            if (hh >= 0 && hh < HDIM && ww >= 0 && ww < WDIM) {
                const float4 v4 = *(const float4*)
                    &g_vt[(size_t)(b * HW + hh * WDIM + ww) * CO + nh * HD + lane * 4];
                float a = sc[ki * 5 + kj];
                acc.x += a * v4.x; acc.y += a * v4.y; acc.z += a * v4.z; acc.w += a * v4.w;
            }
        }
    }

    float av[4] = {acc.x * inv, acc.y * inv, acc.z * inv, acc.w * inv};
#pragma unroll
    for (int i = 0; i < 4; i++) {
        int ch = nh * HD + lane * 4 + i;
        float scl = g1[ch] * rsqrtf(v1[ch] + EPS);
        float val = (av[i] - m1[ch]) * scl + b1[ch];
        g_y1[(size_t)b * CO * HW + (size_t)ch * HW + hw] = fmaxf(val, 0.f);
    }
}

// ---------------- agg GEMM: y2 = BN2(agg_W @ y1), channel-major output -------
__global__ void gemm_agg_kernel(const float* __restrict__ Wm,
                                const float* __restrict__ g2, const float* __restrict__ b2,
                                const float* __restrict__ m2, const float* __restrict__ v2) {
    __shared__ float As[64][17];
    __shared__ float Bs[16][64];

    int tid = threadIdx.x;
    int tx = tid & 15, ty = tid >> 4;
    int o0 = blockIdx.y * 64;
    int n0 = blockIdx.x * 64;
    int bb = n0 / HW;
    int hw0 = n0 % HW;
    const float* xb = g_y1 + (size_t)bb * CO * HW + hw0;

    int arow = tid >> 2, aseg = tid & 3;
    int brow = tid >> 4, bseg = tid & 15;

    float acc[4][4];
#pragma unroll
    for (int i = 0; i < 4; i++)
#pragma unroll
        for (int j = 0; j < 4; j++) acc[i][j] = 0.f;

    for (int k0 = 0; k0 < CO; k0 += 16) {
        float4 av = *(const float4*)&Wm[(o0 + arow) * CO + k0 + aseg * 4];
        float4 bv = *(const float4*)&xb[(size_t)(k0 + brow) * HW + bseg * 4];
        __syncthreads();
        As[arow][aseg * 4 + 0] = av.x;
        As[arow][aseg * 4 + 1] = av.y;
        As[arow][aseg * 4 + 2] = av.z;
        As[arow][aseg * 4 + 3] = av.w;
        *(float4*)&Bs[brow][bseg * 4] = bv;
        __syncthreads();
#pragma unroll
        for (int c = 0; c < 16; c++) {
            float a0 = As[ty * 4 + 0][c];
            float a1 = As[ty * 4 + 1][c];
            float a2 = As[ty * 4 + 2][c];
            float a3 = As[ty * 4 + 3][c];
            float4 b4 = *(float4*)&Bs[c][tx * 4];
            acc[0][0] += a0 * b4.x; acc[0][1] += a0 * b4.y; acc[0][2] += a0 * b4.z; acc[0][3] += a0 * b4.w;
            acc[1][0] += a1 * b4.x; acc[1][1] += a1 * b4.y; acc[1][2] += a1 * b4.z; acc[1][3] += a1 * b4.w;
            acc[2][0] += a2 * b4.x; acc[2][1] += a2 * b4.y; acc[2][2] += a2 * b4.z; acc[2][3] += a2 * b4.w;
            acc[3][0] += a3 * b4.x; acc[3][1] += a3 * b4.y; acc[3][2] += a3 * b4.z; acc[3][3] += a3 * b4.w;
        }
    }
#pragma unroll
    for (int i = 0; i < 4; i++) {
        int o = o0 + ty * 4 + i;
        float scl = g2[o] * rsqrtf(v2[o] + EPS);
        float bo = b2[o] - m2[o] * scl;
        float4 v;
        v.x = acc[i][0] * scl + bo;
        v.y = acc[i][1] * scl + bo;
        v.z = acc[i][2] * scl + bo;
        v.w = acc[i][3] * scl + bo;
        *(float4*)&g_y2[(size_t)bb * CO * HW + (size_t)o * HW + hw0 + tx * 4] = v;
    }
}

// ---------------- zero p accumulator (graph-replay safe) ----------------
__global__ void zero_p_kernel() {
    if (threadIdx.x < NB * SEH) g_p[threadIdx.x] = 0.f;
}

// ---------------- SE stage 1: s = relu(BN(se_Win @ y2)), partial pooling -----
__global__ void se1_kernel(const float* __restrict__ Win,
                           const float* __restrict__ gin, const float* __restrict__ bin,
                           const float* __restrict__ min_, const float* __restrict__ vin) {
    __shared__ float Ws[SEH * CO];
    int tid = threadIdx.x;
    for (int i = tid; i < SEH * CO; i += 256) Ws[i] = Win[i];
    __syncthreads();

    int o = tid >> 4;          // 0..15 output channel
    int ng = tid & 15;         // 0..15 -> 4 columns each (64 n per block)
    int n0 = blockIdx.x * 64;  // 3136 % 64 == 0
    int bb = n0 / HW;
    int hw0 = n0 % HW;
    const float* yb = g_y2 + (size_t)bb * CO * HW + hw0 + ng * 4;

    float4 acc = make_float4(0.f, 0.f, 0.f, 0.f);
    for (int c = 0; c < CO; c++) {
        float wv = Ws[o * CO + c];
        float4 xv = *(const float4*)&yb[(size_t)c * HW];
        acc.x += wv * xv.x; acc.y += wv * xv.y; acc.z += wv * xv.z; acc.w += wv * xv.w;
    }
    float scl = gin[o] * rsqrtf(vin[o] + EPS);
    float bo = bin[o] - min_[o] * scl;
    float4 sv;
    sv.x = fmaxf(acc.x * scl + bo, 0.f);
    sv.y = fmaxf(acc.y * scl + bo, 0.f);
    sv.z = fmaxf(acc.z * scl + bo, 0.f);
    sv.w = fmaxf(acc.w * scl + bo, 0.f);
    *(float4*)&g_s[(size_t)bb * SEH * HW + (size_t)o * HW + hw0 + ng * 4] = sv;

    float psum = sv.x + sv.y + sv.z + sv.w;
#pragma unroll
    for (int m = 8; m; m >>= 1) psum += __shfl_xor_sync(0xffffffffu, psum, m);
    if (ng == 0) atomicAdd(&g_p[bb * SEH + o], psum);
}

// ---------------- SE stage 2: gates ----------------
__global__ void se2_kernel(const float* __restrict__ fc1, const float* __restrict__ fc2) {
    int tid = threadIdx.x;
    if (tid < NB * SEH) {
        int bb = tid >> 4, i = tid & 15;
        float hsum = 0.f;
#pragma unroll
        for (int j = 0; j < SEH; j++) hsum += (g_p[bb * SEH + j] * (1.f / HW)) * fc1[j];
        float hid = fmaxf(hsum, 0.f);
        g_g[tid] = 1.f / (1.f + __expf(-(hid * fc2[i])));
    }
}

// ---------------- SE stage 3: out = BN(se_Wout @ (s * g)) ----------------
__global__ void se3_kernel(const float* __restrict__ Wout,
                           const float* __restrict__ gout, const float* __restrict__ bout,
                           const float* __restrict__ mout, const float* __restrict__ vout,
                           float* __restrict__ out) {
    __shared__ float sjs[SEH][16];  // [j][n_local]
    int tid = threadIdx.x;          // 256 threads = 256 output channels
    int n0 = blockIdx.x * 16;       // 3136 % 16 == 0
    int bb = n0 / HW;
    int hw0 = n0 % HW;

    int j = tid >> 4, nn = tid & 15;
    sjs[j][nn] = g_s[(size_t)bb * SEH * HW + (size_t)j * HW + hw0 + nn] * g_g[bb * SEH + j];
    __syncthreads();

    int o = tid;
    float wreg[SEH];
#pragma unroll
    for (int jj = 0; jj < SEH; jj++) wreg[jj] = Wout[o * SEH + jj];
    float scl = gout[o] * rsqrtf(vout[o] + EPS);
    float bo = bout[o] - mout[o] * scl;
    float* op = out + (size_t)bb * CO * HW + (size_t)o * HW + hw0;
#pragma unroll
    for (int nq = 0; nq < 4; nq++) {
        float4 a = make_float4(0.f, 0.f, 0.f, 0.f);
#pragma unroll
        for (int jj = 0; jj < SEH; jj++) {
            float wv = wreg[jj];
            a.x += wv * sjs[jj][nq * 4 + 0];
            a.y += wv * sjs[jj][nq * 4 + 1];
            a.z += wv * sjs[jj][nq * 4 + 2];
            a.w += wv * sjs[jj][nq * 4 + 3];
        }
        float4 r;
        r.x = a.x * scl + bo; r.y = a.y * scl + bo;
        r.z = a.z * scl + bo; r.w = a.w * scl + bo;
        *(float4*)&op[nq * 4] = r;
    }
}

// ---------------- launch ----------------
extern "C" void kernel_launch(void* const* d_in, const int* in_sizes, int n_in,
                              void* d_out, int out_size) {
    const float* x       = (const float*)d_in[0];
    const float* Wq      = (const float*)d_in[1];
    const float* Wk      = (const float*)d_in[2];
    const float* Wv      = (const float*)d_in[3];
    const float* rel_h   = (const float*)d_in[4];
    const float* rel_w   = (const float*)d_in[5];
    const float* agg_g1  = (const float*)d_in[6];
    const float* agg_b1  = (const float*)d_in[7];
    const float* agg_m1  = (const float*)d_in[8];
    const float* agg_v1  = (const float*)d_in[9];
    const float* agg_W   = (const float*)d_in[10];
    const float* agg_g2  = (const float*)d_in[11];
    const float* agg_b2  = (const float*)d_in[12];
    const float* agg_m2  = (const float*)d_in[13];
    const float* agg_v2  = (const float*)d_in[14];
    const float* se_Win  = (const float*)d_in[15];
    const float* se_g_in = (const float*)d_in[16];
    const float* se_b_in = (const float*)d_in[17];
    const float* se_m_in = (const float*)d_in[18];
    const float* se_v_in = (const float*)d_in[19];
    const float* se_fc1  = (const float*)d_in[20];
    const float* se_fc2  = (const float*)d_in[21];
    const float* se_Wout = (const float*)d_in[22];
    const float* se_g_out= (const float*)d_in[23];
    const float* se_b_out= (const float*)d_in[24];
    const float* se_m_out= (const float*)d_in[25];
    const float* se_v_out= (const float*)d_in[26];
    float* out = (float*)d_out;

    dim3 gqkv(NCOL / 64, CO / 64, 3);
    gemm_qkv_kernel<<<gqkv, 256>>>(Wq, Wk, Wv, x);

    attn_kernel<<<(NB * NHEAD * HW) / 8, 256>>>(rel_h, rel_w, agg_g1, agg_b1, agg_m1, agg_v1);

    dim3 gagg(NCOL / 64, CO / 64);
    gemm_agg_kernel<<<gagg, 256>>>(agg_W, agg_g2, agg_b2, agg_m2, agg_v2);

    zero_p_kernel<<<1, 64>>>();
    se1_kernel<<<NCOL / 64, 256>>>(se_Win, se_g_in, se_b_in, se_m_in, se_v_in);
    se2_kernel<<<1, 64>>>(se_fc1, se_fc2);
    se3_kernel<<<NCOL / 16, 256>>>(se_Wout, se_g_out, se_b_out, se_m_out, se_v_out, out);
}

// round 6
// speedup vs baseline: 1.5737x; 1.5737x over previous
#include <cuda_runtime.h>
#include <math.h>
#include <stdint.h>

#define NB 4
#define CIN 256
#define CO 256
#define HDIM 56
#define WDIM 56
#define HW 3136
#define NCOL 12544     // NB*HW
#define NHEAD 2
#define HD 128
#define EPS 1e-5f
#define SEH 16

// ---------------- scratch (device globals, no allocation) ----------------
__device__ float g_xt[NCOL * CIN];  // x transposed: [n][c]
__device__ float g_qt[NCOL * CO];   // [n][c]
__device__ float g_kt[NCOL * CO];
__device__ float g_vt[NCOL * CO];
__device__ float g_y1[NCOL * CO];   // attn out + BN1 + relu, [n][c]
__device__ float g_y2[NCOL * CO];   // agg out + BN2, [n][c]
__device__ float g_s [NB * SEH * HW]; // channel-major [b][j][hw]
__device__ float g_p [NB * SEH];
__device__ float g_g [NB * SEH];

// ---------------- helpers ----------------
__device__ __forceinline__ uint32_t f2tf32(float f) {
    uint32_t u;
    asm("cvt.rna.tf32.f32 %0, %1;" : "=r"(u) : "f"(f));
    return u;
}

__device__ __forceinline__ void mma_tf32(float* d, const uint32_t* a, const uint32_t* b) {
    asm volatile(
        "mma.sync.aligned.m16n8k8.row.col.f32.tf32.tf32.f32 "
        "{%0,%1,%2,%3}, {%4,%5,%6,%7}, {%8,%9}, {%0,%1,%2,%3};"
        : "+f"(d[0]), "+f"(d[1]), "+f"(d[2]), "+f"(d[3])
        : "r"(a[0]), "r"(a[1]), "r"(a[2]), "r"(a[3]), "r"(b[0]), "r"(b[1]));
}

// ---------------- transpose x: [b][c][hw] -> g_xt [b*hw][c] ----------------
__global__ void transpose_x_kernel(const float* __restrict__ x) {
    __shared__ float t[32][33];
    int b = blockIdx.z;
    int c0 = blockIdx.y * 32, p0 = blockIdx.x * 32;
    int tx = threadIdx.x, ty = threadIdx.y;   // 32 x 8
    const float* xb = x + ((size_t)b * CIN + c0) * HW + p0;
#pragma unroll
    for (int i = 0; i < 4; i++)
        t[ty * 4 + i][tx] = xb[(size_t)(ty * 4 + i) * HW + tx];
    __syncthreads();
    float* ob = g_xt + (size_t)(b * HW + p0) * CIN + c0;
#pragma unroll
    for (int i = 0; i < 4; i++)
        ob[(size_t)(ty * 4 + i) * CIN + tx] = t[tx][ty * 4 + i];
}

// ---------------- tensor-core tf32 GEMM (mma.sync) ----------------
// D[o 128][n 128], K=256.  mode 0: qkv (z-selected), mode 1: agg (+BN2).
// SMEM: fragment-scattered A/B chunks (K=32), reused as padded staging for
// the coalesced [n][o] epilogue.
__global__ __launch_bounds__(256, 1) void gemm_mma_kernel(
    const float* __restrict__ Wq, const float* __restrict__ Wk,
    const float* __restrict__ Wv, const float* __restrict__ Wa,
    const float* __restrict__ g2, const float* __restrict__ b2,
    const float* __restrict__ m2, const float* __restrict__ v2,
    int mode)
{
    __shared__ __align__(16) char smraw[64 * 132 * 4];  // 33792 B
    uint32_t* smA = (uint32_t*)smraw;            // 4096 u32 (128x32 frag layout)
    uint32_t* smB = smA + 4096;                  // 4096 u32
    float* stg = (float*)smraw;                  // 64 x 132 staging (epilogue)

    int tid = threadIdx.x;
    int wid = tid >> 5, lane = tid & 31;
    int warpM = wid >> 2, warpN = wid & 3;       // 2 x 4 warp grid
    int g = lane >> 2, t = lane & 3;

    const float* Wm;
    const float* Bsrc;
    float* outp;
    if (mode == 0) {
        int z = blockIdx.z;
        Wm   = (z == 0) ? Wq : (z == 1 ? Wk : Wv);
        outp = (z == 0) ? g_qt : (z == 1 ? g_kt : g_vt);
        Bsrc = g_xt;
    } else {
        Wm = Wa; Bsrc = g_y1; outp = g_y2;
    }
    int o0 = blockIdx.y * 128;
    int n0 = blockIdx.x * 128;

    float acc[4][4][4];
#pragma unroll
    for (int i = 0; i < 4; i++)
#pragma unroll
        for (int j = 0; j < 4; j++)
#pragma unroll
            for (int s = 0; s < 4; s++) acc[i][j][s] = 0.f;

    int row = tid >> 3, k4 = tid & 7;            // 128 rows, 8 float4 segs; x4 via +32 rows
    float4 pa[4], pb[4];

    // prefetch chunk 0
#pragma unroll
    for (int i = 0; i < 4; i++) {
        pa[i] = *(const float4*)&Wm[(size_t)(o0 + row + 32 * i) * 256 + k4 * 4];
        pb[i] = *(const float4*)&Bsrc[(size_t)(n0 + row + 32 * i) * 256 + k4 * 4];
    }

    for (int c = 0; c < 8; c++) {
        __syncthreads();
        // scatter into fragment layout (tf32-converted)
#pragma unroll
        for (int i = 0; i < 4; i++) {
            int r = row + 32 * i;
            int mtile = r >> 4, rin = r & 15;
            int ntile = r >> 3, nin = r & 7;
            float va[4] = {pa[i].x, pa[i].y, pa[i].z, pa[i].w};
            float vb[4] = {pb[i].x, pb[i].y, pb[i].z, pb[i].w};
#pragma unroll
            for (int e = 0; e < 4; e++) {
                int k = k4 * 4 + e;
                int kt = k >> 3, kin = k & 7;
                int laneA = (rin & 7) * 4 + (kin & 3);
                int slotA = (rin >> 3) + 2 * (kin >> 2);
                smA[((kt * 8 + mtile) * 32 + laneA) * 4 + slotA] = f2tf32(va[e]);
                int laneB = nin * 4 + (kin & 3);
                int slotB = kin >> 2;
                smB[((kt * 16 + ntile) * 32 + laneB) * 2 + slotB] = f2tf32(vb[e]);
            }
        }
        __syncthreads();
        if (c < 7) {
            int k0 = (c + 1) * 32;
#pragma unroll
            for (int i = 0; i < 4; i++) {
                pa[i] = *(const float4*)&Wm[(size_t)(o0 + row + 32 * i) * 256 + k0 + k4 * 4];
                pb[i] = *(const float4*)&Bsrc[(size_t)(n0 + row + 32 * i) * 256 + k0 + k4 * 4];
            }
        }
        // compute on this chunk: 4 k8-steps
#pragma unroll
        for (int ks = 0; ks < 4; ks++) {
            uint32_t af[4][4], bf[4][2];
#pragma unroll
            for (int mt = 0; mt < 4; mt++) {
                uint4 v = *(uint4*)&smA[((ks * 8 + warpM * 4 + mt) * 32 + lane) * 4];
                af[mt][0] = v.x; af[mt][1] = v.y; af[mt][2] = v.z; af[mt][3] = v.w;
            }
#pragma unroll
            for (int nt = 0; nt < 4; nt++) {
                uint2 v = *(uint2*)&smB[((ks * 16 + warpN * 4 + nt) * 32 + lane) * 2];
                bf[nt][0] = v.x; bf[nt][1] = v.y;
            }
#pragma unroll
            for (int mt = 0; mt < 4; mt++)
#pragma unroll
                for (int nt = 0; nt < 4; nt++)
                    mma_tf32(acc[mt][nt], af[mt], bf[nt]);
        }
    }

    // epilogue: stage [n_local 64][o_local 128] halves, coalesced [n][o] store
    int h_of_warp = warpN >> 1;
    for (int h = 0; h < 2; h++) {
        __syncthreads();
        if (h_of_warp == h) {
#pragma unroll
            for (int mt = 0; mt < 4; mt++)
#pragma unroll
                for (int nt = 0; nt < 4; nt++)
#pragma unroll
                    for (int s = 0; s < 4; s++) {
                        int ol = warpM * 64 + mt * 16 + g + (s >> 1) * 8;
                        int nl = (warpN & 1) * 32 + nt * 8 + 2 * t + (s & 1);
                        stg[nl * 132 + ol] = acc[mt][nt][s];
                    }
        }
        __syncthreads();
#pragma unroll
        for (int i = 0; i < 8; i++) {
            int idx = tid + 256 * i;
            int nl = idx >> 5, o4 = idx & 31;
            float4 v = *(float4*)&stg[nl * 132 + o4 * 4];
            if (mode == 1) {
                int ob = o0 + o4 * 4;
                float4 gg = *(const float4*)&g2[ob];
                float4 bb = *(const float4*)&b2[ob];
                float4 mm = *(const float4*)&m2[ob];
                float4 vv = *(const float4*)&v2[ob];
                float s0 = gg.x * rsqrtf(vv.x + EPS);
                float s1 = gg.y * rsqrtf(vv.y + EPS);
                float s2 = gg.z * rsqrtf(vv.z + EPS);
                float s3 = gg.w * rsqrtf(vv.w + EPS);
                v.x = v.x * s0 + (bb.x - mm.x * s0);
                v.y = v.y * s1 + (bb.y - mm.y * s1);
                v.z = v.z * s2 + (bb.z - mm.z * s2);
                v.w = v.w * s3 + (bb.w - mm.w * s3);
            }
            *(float4*)&outp[(size_t)(n0 + h * 64 + nl) * 256 + o0 + o4 * 4] = v;
        }
    }
}

// ---------------- attention: warp per (b, head, h, w) ----------------
__global__ void attn_kernel(const float* __restrict__ rel_h,
                            const float* __restrict__ rel_w,
                            const float* __restrict__ g1, const float* __restrict__ b1,
                            const float* __restrict__ m1, const float* __restrict__ v1) {
    int wid = blockIdx.x * 8 + (threadIdx.x >> 5);
    int lane = threadIdx.x & 31;
    int b = wid / (NHEAD * HW);
    int r = wid % (NHEAD * HW);
    int nh = r / HW;
    int hw = r % HW;
    int h = hw / WDIM, w = hw % WDIM;

    const float4 q4 = *(const float4*)&g_qt[(size_t)(b * HW + hw) * CO + nh * HD + lane * 4];
    const float* rel = nh ? rel_w : rel_h;   // [c][tap], 128*5

    float bias[5];
#pragma unroll
    for (int t = 0; t < 5; t++) {
        int c = lane * 4;
        float p = q4.x * rel[(c + 0) * 5 + t] + q4.y * rel[(c + 1) * 5 + t]
                + q4.z * rel[(c + 2) * 5 + t] + q4.w * rel[(c + 3) * 5 + t];
#pragma unroll
        for (int m = 16; m; m >>= 1) p += __shfl_xor_sync(0xffffffffu, p, m);
        bias[t] = p;
    }

    float sc[25];
#pragma unroll
    for (int ki = 0; ki < 5; ki++) {
        int hh = h + ki - 2;
#pragma unroll
        for (int kj = 0; kj < 5; kj++) {
            int ww = w + kj - 2;
            bool inb = (hh >= 0 && hh < HDIM && ww >= 0 && ww < WDIM);
            float p = 0.f;
            if (inb) {
                const float4 k4 = *(const float4*)
                    &g_kt[(size_t)(b * HW + hh * WDIM + ww) * CO + nh * HD + lane * 4];
                p = q4.x * k4.x + q4.y * k4.y + q4.z * k4.z + q4.w * k4.w;
            }
#pragma unroll
            for (int m = 16; m; m >>= 1) p += __shfl_xor_sync(0xffffffffu, p, m);
            sc[ki * 5 + kj] = (p + bias[nh ? kj : ki]) * 0.08838834764831845f;
        }
    }

    float mx = sc[0];
#pragma unroll
    for (int i = 1; i < 25; i++) mx = fmaxf(mx, sc[i]);
    float sum = 0.f;
#pragma unroll
    for (int i = 0; i < 25; i++) { sc[i] = __expf(sc[i] - mx); sum += sc[i]; }
    float inv = 1.f / sum;

    float4 acc = make_float4(0.f, 0.f, 0.f, 0.f);
#pragma unroll
    for (int ki = 0; ki < 5; ki++) {
        int hh = h + ki - 2;
#pragma unroll
        for (int kj = 0; kj < 5; kj++) {
            int ww = w + kj - 2;
            if (hh >= 0 && hh < HDIM && ww >= 0 && ww < WDIM) {
                const float4 v4 = *(const float4*)
                    &g_vt[(size_t)(b * HW + hh * WDIM + ww) * CO + nh * HD + lane * 4];
                float a = sc[ki * 5 + kj];
                acc.x += a * v4.x; acc.y += a * v4.y; acc.z += a * v4.z; acc.w += a * v4.w;
            }
        }
    }

    // BN1 + relu, n-major coalesced float4 store
    int ch0 = nh * HD + lane * 4;
    float av[4] = {acc.x * inv, acc.y * inv, acc.z * inv, acc.w * inv};
    float4 ov;
    float* pv = &ov.x;
#pragma unroll
    for (int i = 0; i < 4; i++) {
        int ch = ch0 + i;
        float scl = g1[ch] * rsqrtf(v1[ch] + EPS);
        pv[i] = fmaxf((av[i] - m1[ch]) * scl + b1[ch], 0.f);
    }
    *(float4*)&g_y1[(size_t)(b * HW + hw) * CO + ch0] = ov;
}

// ---------------- zero p accumulator ----------------
__global__ void zero_p_kernel() {
    if (threadIdx.x < NB * SEH) g_p[threadIdx.x] = 0.f;
}

// ---------------- SE stage 1: warp per pixel over n-major y2 ----------------
__global__ __launch_bounds__(256) void se1_kernel(const float* __restrict__ Win,
                           const float* __restrict__ gin, const float* __restrict__ bin,
                           const float* __restrict__ min_, const float* __restrict__ vin) {
    __shared__ float Ws[SEH * CO];
    __shared__ float pool[SEH];
    int tid = threadIdx.x, wid = tid >> 5, lane = tid & 31;
    for (int i = tid; i < SEH * CO; i += 256) Ws[i] = Win[i];
    if (tid < SEH) pool[tid] = 0.f;
    __syncthreads();

    int n0 = blockIdx.x * 64;
    int bb = n0 / HW;
    int hwb = n0 % HW;

    float scl = 0.f, bo = 0.f;
    if (lane < SEH) {
        scl = gin[lane] * rsqrtf(vin[lane] + EPS);
        bo = bin[lane] - min_[lane] * scl;
    }

    for (int px = wid; px < 64; px += 8) {
        const float* y = &g_y2[(size_t)(n0 + px) * CO];
        float4 v0 = *(const float4*)&y[lane * 4];
        float4 v1 = *(const float4*)&y[128 + lane * 4];
        float sj_me = 0.f;
#pragma unroll
        for (int j = 0; j < SEH; j++) {
            const float* wj = &Ws[j * CO];
            float4 w0 = *(const float4*)&wj[lane * 4];
            float4 w1 = *(const float4*)&wj[128 + lane * 4];
            float p = v0.x * w0.x + v0.y * w0.y + v0.z * w0.z + v0.w * w0.w
                    + v1.x * w1.x + v1.y * w1.y + v1.z * w1.z + v1.w * w1.w;
#pragma unroll
            for (int m = 16; m; m >>= 1) p += __shfl_xor_sync(0xffffffffu, p, m);
            if (lane == j) sj_me = p;
        }
        if (lane < SEH) {
            float sv = fmaxf(sj_me * scl + bo, 0.f);
            g_s[(size_t)bb * SEH * HW + (size_t)lane * HW + (hwb + px)] = sv;
            atomicAdd(&pool[lane], sv);
        }
    }
    __syncthreads();
    if (tid < SEH) atomicAdd(&g_p[bb * SEH + tid], pool[tid]);
}

// ---------------- SE stage 2: gates ----------------
__global__ void se2_kernel(const float* __restrict__ fc1, const float* __restrict__ fc2) {
    int tid = threadIdx.x;
    if (tid < NB * SEH) {
        int bb = tid >> 4, i = tid & 15;
        float hsum = 0.f;
#pragma unroll
        for (int j = 0; j < SEH; j++) hsum += (g_p[bb * SEH + j] * (1.f / HW)) * fc1[j];
        float hid = fmaxf(hsum, 0.f);
        g_g[tid] = 1.f / (1.f + __expf(-(hid * fc2[i])));
    }
}

// ---------------- SE stage 3: out = BN(se_Wout @ (s * g)), channel-major ----
__global__ void se3_kernel(const float* __restrict__ Wout,
                           const float* __restrict__ gout, const float* __restrict__ bout,
                           const float* __restrict__ mout, const float* __restrict__ vout,
                           float* __restrict__ out) {
    __shared__ float sjs[SEH][16];
    int tid = threadIdx.x;
    int n0 = blockIdx.x * 16;
    int bb = n0 / HW;
    int hw0 = n0 % HW;

    int j = tid >> 4, nn = tid & 15;
    sjs[j][nn] = g_s[(size_t)bb * SEH * HW + (size_t)j * HW + hw0 + nn] * g_g[bb * SEH + j];
    __syncthreads();

    int o = tid;
    float wreg[SEH];
#pragma unroll
    for (int jj = 0; jj < SEH; jj++) wreg[jj] = Wout[o * SEH + jj];
    float scl = gout[o] * rsqrtf(vout[o] + EPS);
    float bo = bout[o] - mout[o] * scl;
    float* op = out + (size_t)bb * CO * HW + (size_t)o * HW + hw0;
#pragma unroll
    for (int nq = 0; nq < 4; nq++) {
        float4 a = make_float4(0.f, 0.f, 0.f, 0.f);
#pragma unroll
        for (int jj = 0; jj < SEH; jj++) {
            float wv = wreg[jj];
            a.x += wv * sjs[jj][nq * 4 + 0];
            a.y += wv * sjs[jj][nq * 4 + 1];
            a.z += wv * sjs[jj][nq * 4 + 2];
            a.w += wv * sjs[jj][nq * 4 + 3];
        }
        float4 r;
        r.x = a.x * scl + bo; r.y = a.y * scl + bo;
        r.z = a.z * scl + bo; r.w = a.w * scl + bo;
        *(float4*)&op[nq * 4] = r;
    }
}

// ---------------- launch ----------------
extern "C" void kernel_launch(void* const* d_in, const int* in_sizes, int n_in,
                              void* d_out, int out_size) {
    const float* x       = (const float*)d_in[0];
    const float* Wq      = (const float*)d_in[1];
    const float* Wk      = (const float*)d_in[2];
    const float* Wv      = (const float*)d_in[3];
    const float* rel_h   = (const float*)d_in[4];
    const float* rel_w   = (const float*)d_in[5];
    const float* agg_g1  = (const float*)d_in[6];
    const float* agg_b1  = (const float*)d_in[7];
    const float* agg_m1  = (const float*)d_in[8];
    const float* agg_v1  = (const float*)d_in[9];
    const float* agg_W   = (const float*)d_in[10];
    const float* agg_g2  = (const float*)d_in[11];
    const float* agg_b2  = (const float*)d_in[12];
    const float* agg_m2  = (const float*)d_in[13];
    const float* agg_v2  = (const float*)d_in[14];
    const float* se_Win  = (const float*)d_in[15];
    const float* se_g_in = (const float*)d_in[16];
    const float* se_b_in = (const float*)d_in[17];
    const float* se_m_in = (const float*)d_in[18];
    const float* se_v_in = (const float*)d_in[19];
    const float* se_fc1  = (const float*)d_in[20];
    const float* se_fc2  = (const float*)d_in[21];
    const float* se_Wout = (const float*)d_in[22];
    const float* se_g_out= (const float*)d_in[23];
    const float* se_b_out= (const float*)d_in[24];
    const float* se_m_out= (const float*)d_in[25];
    const float* se_v_out= (const float*)d_in[26];
    float* out = (float*)d_out;

    transpose_x_kernel<<<dim3(98, 8, 4), dim3(32, 8)>>>(x);

    gemm_mma_kernel<<<dim3(98, 2, 3), 256>>>(Wq, Wk, Wv, nullptr,
                                             nullptr, nullptr, nullptr, nullptr, 0);

    attn_kernel<<<(NB * NHEAD * HW) / 8, 256>>>(rel_h, rel_w, agg_g1, agg_b1, agg_m1, agg_v1);

    gemm_mma_kernel<<<dim3(98, 2, 1), 256>>>(nullptr, nullptr, nullptr, agg_W,
                                             agg_g2, agg_b2, agg_m2, agg_v2, 1);

    zero_p_kernel<<<1, 64>>>();
    se1_kernel<<<NCOL / 64, 256>>>(se_Win, se_g_in, se_b_in, se_m_in, se_v_in);
    se2_kernel<<<1, 64>>>(se_fc1, se_fc2);
    se3_kernel<<<NCOL / 16, 256>>>(se_Wout, se_g_out, se_b_out, se_m_out, se_v_out, out);
}

// round 7
// speedup vs baseline: 1.6883x; 1.0728x over previous
#include <cuda_runtime.h>
#include <math.h>
#include <stdint.h>

#define NB 4
#define CIN 256
#define CO 256
#define HDIM 56
#define WDIM 56
#define HW 3136
#define NCOL 12544     // NB*HW
#define NHEAD 2
#define HD 128
#define EPS 1e-5f
#define SEH 16

// ---------------- scratch (device globals, no allocation) ----------------
__device__ float g_xt[NCOL * CIN];  // x transposed: [n][c]
__device__ float g_qt[NCOL * CO];   // [n][c]
__device__ float g_kt[NCOL * CO];
__device__ float g_vt[NCOL * CO];
__device__ float g_y1[NCOL * CO];   // attn out + BN1 + relu, [n][c]
__device__ float g_y2[NCOL * CO];   // agg out + BN2, [n][c]
__device__ float g_s [NB * SEH * HW]; // channel-major [b][j][hw]
__device__ float g_p [NB * SEH];
__device__ float g_g [NB * SEH];

// ---------------- helpers ----------------
__device__ __forceinline__ uint32_t f2tf32(float f) {
    uint32_t u;
    asm("cvt.rna.tf32.f32 %0, %1;" : "=r"(u) : "f"(f));
    return u;
}

__device__ __forceinline__ void mma_tf32(float* d, const uint32_t* a, const uint32_t* b) {
    asm volatile(
        "mma.sync.aligned.m16n8k8.row.col.f32.tf32.tf32.f32 "
        "{%0,%1,%2,%3}, {%4,%5,%6,%7}, {%8,%9}, {%0,%1,%2,%3};"
        : "+f"(d[0]), "+f"(d[1]), "+f"(d[2]), "+f"(d[3])
        : "r"(a[0]), "r"(a[1]), "r"(a[2]), "r"(a[3]), "r"(b[0]), "r"(b[1]));
}

// ---------------- transpose x: [b][c][hw] -> g_xt [b*hw][c] ----------------
__global__ void transpose_x_kernel(const float* __restrict__ x) {
    __shared__ float t[32][33];
    int b = blockIdx.z;
    int c0 = blockIdx.y * 32, p0 = blockIdx.x * 32;
    int tx = threadIdx.x, ty = threadIdx.y;   // 32 x 8
    const float* xb = x + ((size_t)b * CIN + c0) * HW + p0;
#pragma unroll
    for (int i = 0; i < 4; i++)
        t[ty * 4 + i][tx] = xb[(size_t)(ty * 4 + i) * HW + tx];
    __syncthreads();
    float* ob = g_xt + (size_t)(b * HW + p0) * CIN + c0;
#pragma unroll
    for (int i = 0; i < 4; i++)
        ob[(size_t)(ty * 4 + i) * CIN + tx] = t[tx][ty * 4 + i];
}

// ---------------- tensor-core tf32 GEMM, double-buffered K=16 chunks -------
// D[o 128][n 128], K=256.  mode 0: qkv (z-selected), mode 1: agg (+BN2).
__global__ __launch_bounds__(256, 2) void gemm_mma_kernel(
    const float* __restrict__ Wq, const float* __restrict__ Wk,
    const float* __restrict__ Wv, const float* __restrict__ Wa,
    const float* __restrict__ g2, const float* __restrict__ b2,
    const float* __restrict__ m2, const float* __restrict__ v2,
    int mode)
{
    // union: 2 double-buffer chunks (2 x 16KB) OR epilogue staging (33792 B)
    __shared__ __align__(16) char smraw[33792];
    float* stg = (float*)smraw;

    int tid = threadIdx.x;
    int wid = tid >> 5, lane = tid & 31;
    int warpM = wid >> 2, warpN = wid & 3;       // 2 x 4 warp grid
    int g = lane >> 2, t = lane & 3;

    const float* Wm;
    const float* Bsrc;
    float* outp;
    if (mode == 0) {
        int z = blockIdx.z;
        Wm   = (z == 0) ? Wq : (z == 1 ? Wk : Wv);
        outp = (z == 0) ? g_qt : (z == 1 ? g_kt : g_vt);
        Bsrc = g_xt;
    } else {
        Wm = Wa; Bsrc = g_y1; outp = g_y2;
    }
    int o0 = blockIdx.y * 128;
    int n0 = blockIdx.x * 128;

    float acc[4][4][4];
#pragma unroll
    for (int i = 0; i < 4; i++)
#pragma unroll
        for (int j = 0; j < 4; j++)
#pragma unroll
            for (int s = 0; s < 4; s++) acc[i][j][s] = 0.f;

    // producer role: tid<128 -> A (weights), tid>=128 -> B (activations)
    bool isA = tid < 128;
    int t2 = isA ? tid : tid - 128;
    int low3 = t2 & 7, mid3 = (t2 >> 3) & 7, kt = t2 >> 6;   // kt in 0..1
    const float* srcRow0;
    const float* srcRow1;
    if (isA) {
        int rowA = o0 + mid3 * 16 + low3;
        srcRow0 = Wm + (size_t)rowA * 256;
        srcRow1 = srcRow0 + 8 * 256;
    } else {
        int rowB = n0 + mid3 * 8 + low3;
        srcRow0 = Bsrc + (size_t)rowB * 256;
        srcRow1 = srcRow0 + 64 * 256;
    }
    int kOff = kt * 8;

    float4 p0, p1, p2, p3;

#define LOADC(c) do { \
        int kb = (c) * 16 + kOff; \
        p0 = *(const float4*)(srcRow0 + kb); \
        p1 = *(const float4*)(srcRow0 + kb + 4); \
        p2 = *(const float4*)(srcRow1 + kb); \
        p3 = *(const float4*)(srcRow1 + kb + 4); \
    } while (0)

#define SCATTER(bufi) do { \
        if (isA) { \
            uint4* Ab = (uint4*)(smraw + (bufi) * 16384); \
            const float* e0 = &p0.x; const float* e1 = &p1.x; \
            const float* e2 = &p2.x; const float* e3 = &p3.x; \
            _Pragma("unroll") \
            for (int j = 0; j < 4; j++) { \
                int idx = (kt * 8 + mid3) * 32 + low3 * 4 + j; \
                idx ^= (idx >> 3) & 3; \
                Ab[idx] = make_uint4(f2tf32(e0[j]), f2tf32(e2[j]), \
                                     f2tf32(e1[j]), f2tf32(e3[j])); \
            } \
        } else { \
            uint2* Bb = (uint2*)(smraw + (bufi) * 16384 + 8192); \
            const float* e0 = &p0.x; const float* e1 = &p1.x; \
            const float* e2 = &p2.x; const float* e3 = &p3.x; \
            _Pragma("unroll") \
            for (int j = 0; j < 4; j++) { \
                int idx = (kt * 16 + mid3) * 32 + low3 * 4 + j; \
                idx ^= (idx >> 4) & 3; \
                Bb[idx] = make_uint2(f2tf32(e0[j]), f2tf32(e1[j])); \
                int idx2 = (kt * 16 + mid3 + 8) * 32 + low3 * 4 + j; \
                idx2 ^= (idx2 >> 4) & 3; \
                Bb[idx2] = make_uint2(f2tf32(e2[j]), f2tf32(e3[j])); \
            } \
        } \
    } while (0)

    LOADC(0);
    SCATTER(0);
    LOADC(1);
    __syncthreads();

    for (int c = 0; c < 16; c++) {
        if (c < 15) SCATTER((c + 1) & 1);
        if (c < 14) LOADC(c + 2);
        // compute chunk c from buf[c&1]
        {
            const uint4* Ab = (const uint4*)(smraw + (c & 1) * 16384);
            const uint2* Bb = (const uint2*)(smraw + (c & 1) * 16384 + 8192);
#pragma unroll
            for (int ks = 0; ks < 2; ks++) {
                uint32_t af[4][4], bf[4][2];
#pragma unroll
                for (int mt = 0; mt < 4; mt++) {
                    int idx = (ks * 8 + warpM * 4 + mt) * 32 + lane;
                    idx ^= (idx >> 3) & 3;
                    uint4 v = Ab[idx];
                    af[mt][0] = v.x; af[mt][1] = v.y; af[mt][2] = v.z; af[mt][3] = v.w;
                }
#pragma unroll
                for (int nt = 0; nt < 4; nt++) {
                    int idx = (ks * 16 + warpN * 4 + nt) * 32 + lane;
                    idx ^= (idx >> 4) & 3;
                    uint2 v = Bb[idx];
                    bf[nt][0] = v.x; bf[nt][1] = v.y;
                }
#pragma unroll
                for (int mt = 0; mt < 4; mt++)
#pragma unroll
                    for (int nt = 0; nt < 4; nt++)
                        mma_tf32(acc[mt][nt], af[mt], bf[nt]);
            }
        }
        __syncthreads();
    }

    // epilogue: stage [n_local 64][o_local 128] halves, coalesced [n][o] store
    int h_of_warp = warpN >> 1;
    for (int h = 0; h < 2; h++) {
        __syncthreads();
        if (h_of_warp == h) {
#pragma unroll
            for (int mt = 0; mt < 4; mt++)
#pragma unroll
                for (int nt = 0; nt < 4; nt++)
#pragma unroll
                    for (int s = 0; s < 4; s++) {
                        int ol = warpM * 64 + mt * 16 + g + (s >> 1) * 8;
                        int nl = (warpN & 1) * 32 + nt * 8 + 2 * t + (s & 1);
                        stg[nl * 132 + ol] = acc[mt][nt][s];
                    }
        }
        __syncthreads();
#pragma unroll
        for (int i = 0; i < 8; i++) {
            int idx = tid + 256 * i;
            int nl = idx >> 5, o4 = idx & 31;
            float4 v = *(float4*)&stg[nl * 132 + o4 * 4];
            if (mode == 1) {
                int ob = o0 + o4 * 4;
                float4 gg = *(const float4*)&g2[ob];
                float4 bb = *(const float4*)&b2[ob];
                float4 mm = *(const float4*)&m2[ob];
                float4 vv = *(const float4*)&v2[ob];
                float s0 = gg.x * rsqrtf(vv.x + EPS);
                float s1 = gg.y * rsqrtf(vv.y + EPS);
                float s2 = gg.z * rsqrtf(vv.z + EPS);
                float s3 = gg.w * rsqrtf(vv.w + EPS);
                v.x = v.x * s0 + (bb.x - mm.x * s0);
                v.y = v.y * s1 + (bb.y - mm.y * s1);
                v.z = v.z * s2 + (bb.z - mm.z * s2);
                v.w = v.w * s3 + (bb.w - mm.w * s3);
            }
            *(float4*)&outp[(size_t)(n0 + h * 64 + nl) * 256 + o0 + o4 * 4] = v;
        }
    }
#undef LOADC
#undef SCATTER
}

// ---------------- attention: CTA per (b, head, 4x4 pixel tile) --------------
// smem-tiled: k tile (8x8 with halo) staged, then overwritten by v tile.
// OOB positions are zero-filled, which exactly reproduces the reference's
// zero-padded k/v (+rel bias on scores, 0 contribution from v).
__global__ __launch_bounds__(256) void attn_kernel(
                            const float* __restrict__ rel_h,
                            const float* __restrict__ rel_w,
                            const float* __restrict__ g1, const float* __restrict__ b1,
                            const float* __restrict__ m1, const float* __restrict__ v1) {
    __shared__ __align__(16) float kv[64][128];   // 32 KB tile (k then v)
    __shared__ float attnw[16][26];
    __shared__ __align__(16) float relS[5][128];

    int tid = threadIdx.x, wid = tid >> 5, lane = tid & 31;
    int tile = blockIdx.x;           // 0..195
    int th = tile / 14, tw = tile % 14;
    int nh = blockIdx.y, b = blockIdx.z;
    int h0 = th * 4, w0 = tw * 4;

    // cache rel bias table as [tap][c]
    const float* rel = nh ? rel_w : rel_h;   // [c][tap], 128*5
    for (int i = tid; i < 640; i += 256) {
        int c = i / 5, tp = i % 5;
        relS[tp][c] = rel[i];
    }

    // ---- load k tile (8x8 halo positions x 128 ch) ----
    const float* kbase = g_kt + (size_t)b * HW * CO + nh * HD;
#pragma unroll
    for (int i = 0; i < 8; i++) {
        int idx = tid + 256 * i;
        int pos = idx >> 5, c4 = idx & 31;
        int py = pos >> 3, px = pos & 7;
        int hh = h0 - 2 + py, ww = w0 - 2 + px;
        float4 v = make_float4(0.f, 0.f, 0.f, 0.f);
        if ((unsigned)hh < HDIM && (unsigned)ww < WDIM)
            v = *(const float4*)&kbase[(size_t)(hh * WDIM + ww) * CO + c4 * 4];
        *(float4*)&kv[pos][c4 * 4] = v;
    }
    __syncthreads();

    // ---- phase 1: scores + softmax (2 pixels per warp) ----
#pragma unroll
    for (int pp = 0; pp < 2; pp++) {
        int pi = wid * 2 + pp;
        int py = pi >> 2, px = pi & 3;
        int hw = (h0 + py) * WDIM + (w0 + px);
        const float4 q4 = *(const float4*)&g_qt[(size_t)(b * HW + hw) * CO + nh * HD + lane * 4];

        float bias[5];
#pragma unroll
        for (int tp = 0; tp < 5; tp++) {
            float4 r4 = *(const float4*)&relS[tp][lane * 4];
            float p = q4.x * r4.x + q4.y * r4.y + q4.z * r4.z + q4.w * r4.w;
#pragma unroll
            for (int m = 16; m; m >>= 1) p += __shfl_xor_sync(0xffffffffu, p, m);
            bias[tp] = p;
        }

        float sc_mine = -1e30f;   // lane i (<25) keeps score i
#pragma unroll
        for (int t25 = 0; t25 < 25; t25++) {
            int ki = t25 / 5, kj = t25 % 5;
            int pos = (py + ki) * 8 + px + kj;
            float4 k4 = *(const float4*)&kv[pos][lane * 4];
            float p = q4.x * k4.x + q4.y * k4.y + q4.z * k4.z + q4.w * k4.w;
#pragma unroll
            for (int m = 16; m; m >>= 1) p += __shfl_xor_sync(0xffffffffu, p, m);
            float s = (p + bias[nh ? kj : ki]) * 0.08838834764831845f;
            if (lane == t25) sc_mine = s;
        }
        float mx = sc_mine;
#pragma unroll
        for (int m = 16; m; m >>= 1) mx = fmaxf(mx, __shfl_xor_sync(0xffffffffu, mx, m));
        float e = (lane < 25) ? __expf(sc_mine - mx) : 0.f;
        float ssum = e;
#pragma unroll
        for (int m = 16; m; m >>= 1) ssum += __shfl_xor_sync(0xffffffffu, ssum, m);
        if (lane < 25) attnw[pi][lane] = e / ssum;
    }
    __syncthreads();

    // ---- overwrite tile with v ----
    const float* vbase = g_vt + (size_t)b * HW * CO + nh * HD;
#pragma unroll
    for (int i = 0; i < 8; i++) {
        int idx = tid + 256 * i;
        int pos = idx >> 5, c4 = idx & 31;
        int py = pos >> 3, px = pos & 7;
        int hh = h0 - 2 + py, ww = w0 - 2 + px;
        float4 v = make_float4(0.f, 0.f, 0.f, 0.f);
        if ((unsigned)hh < HDIM && (unsigned)ww < WDIM)
            v = *(const float4*)&vbase[(size_t)(hh * WDIM + ww) * CO + c4 * 4];
        *(float4*)&kv[pos][c4 * 4] = v;
    }
    __syncthreads();

    // ---- phase 2: weighted sum + BN1 + relu ----
#pragma unroll
    for (int pp = 0; pp < 2; pp++) {
        int pi = wid * 2 + pp;
        int py = pi >> 2, px = pi & 3;
        int hw = (h0 + py) * WDIM + (w0 + px);
        float4 acc = make_float4(0.f, 0.f, 0.f, 0.f);
#pragma unroll
        for (int t25 = 0; t25 < 25; t25++) {
            int ki = t25 / 5, kj = t25 % 5;
            int pos = (py + ki) * 8 + px + kj;
            float a = attnw[pi][t25];
            float4 v4 = *(const float4*)&kv[pos][lane * 4];
            acc.x += a * v4.x; acc.y += a * v4.y; acc.z += a * v4.z; acc.w += a * v4.w;
        }
        int ch0 = nh * HD + lane * 4;
        float av[4] = {acc.x, acc.y, acc.z, acc.w};
        float4 ov;
        float* pv = &ov.x;
#pragma unroll
        for (int i = 0; i < 4; i++) {
            int ch = ch0 + i;
            float scl = g1[ch] * rsqrtf(v1[ch] + EPS);
            pv[i] = fmaxf((av[i] - m1[ch]) * scl + b1[ch], 0.f);
        }
        *(float4*)&g_y1[(size_t)(b * HW + hw) * CO + ch0] = ov;
    }
}

// ---------------- zero p accumulator ----------------
__global__ void zero_p_kernel() {
    if (threadIdx.x < NB * SEH) g_p[threadIdx.x] = 0.f;
}

// ---------------- SE stage 1: warp per pixel over n-major y2 ----------------
__global__ __launch_bounds__(256) void se1_kernel(const float* __restrict__ Win,
                           const float* __restrict__ gin, const float* __restrict__ bin,
                           const float* __restrict__ min_, const float* __restrict__ vin) {
    __shared__ float Ws[SEH * CO];
    __shared__ float pool[SEH];
    int tid = threadIdx.x, wid = tid >> 5, lane = tid & 31;
    for (int i = tid; i < SEH * CO; i += 256) Ws[i] = Win[i];
    if (tid < SEH) pool[tid] = 0.f;
    __syncthreads();

    int n0 = blockIdx.x * 64;
    int bb = n0 / HW;
    int hwb = n0 % HW;

    float scl = 0.f, bo = 0.f;
    if (lane < SEH) {
        scl = gin[lane] * rsqrtf(vin[lane] + EPS);
        bo = bin[lane] - min_[lane] * scl;
    }

    for (int px = wid; px < 64; px += 8) {
        const float* y = &g_y2[(size_t)(n0 + px) * CO];
        float4 v0 = *(const float4*)&y[lane * 4];
        float4 v1 = *(const float4*)&y[128 + lane * 4];
        float sj_me = 0.f;
#pragma unroll
        for (int j = 0; j < SEH; j++) {
            const float* wj = &Ws[j * CO];
            float4 w0 = *(const float4*)&wj[lane * 4];
            float4 w1 = *(const float4*)&wj[128 + lane * 4];
            float p = v0.x * w0.x + v0.y * w0.y + v0.z * w0.z + v0.w * w0.w
                    + v1.x * w1.x + v1.y * w1.y + v1.z * w1.z + v1.w * w1.w;
#pragma unroll
            for (int m = 16; m; m >>= 1) p += __shfl_xor_sync(0xffffffffu, p, m);
            if (lane == j) sj_me = p;
        }
        if (lane < SEH) {
            float sv = fmaxf(sj_me * scl + bo, 0.f);
            g_s[(size_t)bb * SEH * HW + (size_t)lane * HW + (hwb + px)] = sv;
            atomicAdd(&pool[lane], sv);
        }
    }
    __syncthreads();
    if (tid < SEH) atomicAdd(&g_p[bb * SEH + tid], pool[tid]);
}

// ---------------- SE stage 2: gates ----------------
__global__ void se2_kernel(const float* __restrict__ fc1, const float* __restrict__ fc2) {
    int tid = threadIdx.x;
    if (tid < NB * SEH) {
        int bb = tid >> 4, i = tid & 15;
        float hsum = 0.f;
#pragma unroll
        for (int j = 0; j < SEH; j++) hsum += (g_p[bb * SEH + j] * (1.f / HW)) * fc1[j];
        float hid = fmaxf(hsum, 0.f);
        g_g[tid] = 1.f / (1.f + __expf(-(hid * fc2[i])));
    }
}

// ---------------- SE stage 3: out = BN(se_Wout @ (s * g)), channel-major ----
__global__ void se3_kernel(const float* __restrict__ Wout,
                           const float* __restrict__ gout, const float* __restrict__ bout,
                           const float* __restrict__ mout, const float* __restrict__ vout,
                           float* __restrict__ out) {
    __shared__ float sjs[SEH][16];
    int tid = threadIdx.x;
    int n0 = blockIdx.x * 16;
    int bb = n0 / HW;
    int hw0 = n0 % HW;

    int j = tid >> 4, nn = tid & 15;
    sjs[j][nn] = g_s[(size_t)bb * SEH * HW + (size_t)j * HW + hw0 + nn] * g_g[bb * SEH + j];
    __syncthreads();

    int o = tid;
    float wreg[SEH];
#pragma unroll
    for (int jj = 0; jj < SEH; jj++) wreg[jj] = Wout[o * SEH + jj];
    float scl = gout[o] * rsqrtf(vout[o] + EPS);
    float bo = bout[o] - mout[o] * scl;
    float* op = out + (size_t)bb * CO * HW + (size_t)o * HW + hw0;
#pragma unroll
    for (int nq = 0; nq < 4; nq++) {
        float4 a = make_float4(0.f, 0.f, 0.f, 0.f);
#pragma unroll
        for (int jj = 0; jj < SEH; jj++) {
            float wv = wreg[jj];
            a.x += wv * sjs[jj][nq * 4 + 0];
            a.y += wv * sjs[jj][nq * 4 + 1];
            a.z += wv * sjs[jj][nq * 4 + 2];
            a.w += wv * sjs[jj][nq * 4 + 3];
        }
        float4 r;
        r.x = a.x * scl + bo; r.y = a.y * scl + bo;
        r.z = a.z * scl + bo; r.w = a.w * scl + bo;
        *(float4*)&op[nq * 4] = r;
    }
}

// ---------------- launch ----------------
extern "C" void kernel_launch(void* const* d_in, const int* in_sizes, int n_in,
                              void* d_out, int out_size) {
    const float* x       = (const float*)d_in[0];
    const float* Wq      = (const float*)d_in[1];
    const float* Wk      = (const float*)d_in[2];
    const float* Wv      = (const float*)d_in[3];
    const float* rel_h   = (const float*)d_in[4];
    const float* rel_w   = (const float*)d_in[5];
    const float* agg_g1  = (const float*)d_in[6];
    const float* agg_b1  = (const float*)d_in[7];
    const float* agg_m1  = (const float*)d_in[8];
    const float* agg_v1  = (const float*)d_in[9];
    const float* agg_W   = (const float*)d_in[10];
    const float* agg_g2  = (const float*)d_in[11];
    const float* agg_b2  = (const float*)d_in[12];
    const float* agg_m2  = (const float*)d_in[13];
    const float* agg_v2  = (const float*)d_in[14];
    const float* se_Win  = (const float*)d_in[15];
    const float* se_g_in = (const float*)d_in[16];
    const float* se_b_in = (const float*)d_in[17];
    const float* se_m_in = (const float*)d_in[18];
    const float* se_v_in = (const float*)d_in[19];
    const float* se_fc1  = (const float*)d_in[20];
    const float* se_fc2  = (const float*)d_in[21];
    const float* se_Wout = (const float*)d_in[22];
    const float* se_g_out= (const float*)d_in[23];
    const float* se_b_out= (const float*)d_in[24];
    const float* se_m_out= (const float*)d_in[25];
    const float* se_v_out= (const float*)d_in[26];
    float* out = (float*)d_out;

    transpose_x_kernel<<<dim3(98, 8, 4), dim3(32, 8)>>>(x);

    gemm_mma_kernel<<<dim3(98, 2, 3), 256>>>(Wq, Wk, Wv, nullptr,
                                             nullptr, nullptr, nullptr, nullptr, 0);

    attn_kernel<<<dim3(196, NHEAD, NB), 256>>>(rel_h, rel_w, agg_g1, agg_b1, agg_m1, agg_v1);

    gemm_mma_kernel<<<dim3(98, 2, 1), 256>>>(nullptr, nullptr, nullptr, agg_W,
                                             agg_g2, agg_b2, agg_m2, agg_v2, 1);

    zero_p_kernel<<<1, 64>>>();
    se1_kernel<<<NCOL / 64, 256>>>(se_Win, se_g_in, se_b_in, se_m_in, se_v_in);
    se2_kernel<<<1, 64>>>(se_fc1, se_fc2);
    se3_kernel<<<NCOL / 16, 256>>>(se_Wout, se_g_out, se_b_out, se_m_out, se_v_out, out);
}